// round 1
// baseline (speedup 1.0000x reference)
#include <cuda_runtime.h>

#define N 2048
#define K 16
#define BATCH 16384
#define ROWS_PER_BLOCK 16
#define THREADS 256

// Scratch for composed factors (static device globals: allocation-free)
__device__ float g_W01[N * K];
// Final composed weights in [t][m][rho] layout: index (t*16+m)*128 + rho
__device__ float g_Wfin[K * K * 128];

// ---------------------------------------------------------------------------
// Precompute stage 1: W01 = W0 @ W1
// W0: r -> a = (r + 128*k0) % N,      val0[r*16+k0]
// W1: a -> b = (a + 128*k1 + 1) % N,  val1[a*16+k1]
// => W01[r, s] at b = (r + 128*s + 1) % N,  s = (k0+k1) & 15
// ---------------------------------------------------------------------------
__global__ void k_compose1(const float* __restrict__ v0, const float* __restrict__ v1) {
    int r = blockIdx.x * blockDim.x + threadIdx.x;
    if (r >= N) return;
    float acc[K];
#pragma unroll
    for (int s = 0; s < K; s++) acc[s] = 0.f;
#pragma unroll
    for (int k0 = 0; k0 < K; k0++) {
        float a = v0[r * K + k0];
        int arow = (r + 128 * k0) & (N - 1);
        const float* p = v1 + arow * K;
#pragma unroll
        for (int s = 0; s < K; s++) {
            acc[s] = fmaf(a, p[(s - k0) & (K - 1)], acc[s]);
        }
    }
#pragma unroll
    for (int s = 0; s < K; s++) g_W01[r * K + s] = acc[s];
}

// ---------------------------------------------------------------------------
// Precompute stage 2: W012 = W01 @ W2, folded with `scaling`, written directly
// into the main kernel's [t][m][rho] layout.
// W01: r -> b = (r + 128*s01 + 1) % N
// W2:  b -> c = (b + 128*k2 + 2) % N  => c = (r + 128*s + 3) % N, k2=(s-s01)&15
// Main-kernel mapping: r = rho + 128*t, m = (t + s) & 15
// ---------------------------------------------------------------------------
__global__ void k_compose2(const float* __restrict__ v2, const float* __restrict__ scaling) {
    int r = blockIdx.x * blockDim.x + threadIdx.x;
    if (r >= N) return;
    float sc = scaling[0];
    float acc[K];
#pragma unroll
    for (int s = 0; s < K; s++) acc[s] = 0.f;
#pragma unroll
    for (int s01 = 0; s01 < K; s01++) {
        float a = g_W01[r * K + s01];
        int brow = (r + 128 * s01 + 1) & (N - 1);
        const float* p = v2 + brow * K;
#pragma unroll
        for (int s = 0; s < K; s++) {
            acc[s] = fmaf(a, p[(s - s01) & (K - 1)], acc[s]);
        }
    }
    int rho = r & 127;
    int t = r >> 7;
#pragma unroll
    for (int s = 0; s < K; s++) {
        int m = (t + s) & (K - 1);
        g_Wfin[(t * 16 + m) * 128 + rho] = sc * acc[s];
    }
}

// ---------------------------------------------------------------------------
// Packed f32x2 helpers (dual-rate FMA on sm_103a, only reachable via PTX)
// ---------------------------------------------------------------------------
__device__ __forceinline__ unsigned long long fma2(unsigned long long a,
                                                   unsigned long long b,
                                                   unsigned long long c) {
    unsigned long long d;
    asm("fma.rn.f32x2 %0, %1, %2, %3;" : "=l"(d) : "l"(a), "l"(b), "l"(c));
    return d;
}
__device__ __forceinline__ unsigned long long pack2(float lo, float hi) {
    unsigned long long r;
    asm("mov.b64 %0, {%1, %2};" : "=l"(r) : "f"(lo), "f"(hi));
    return r;
}
__device__ __forceinline__ void unpack2(unsigned long long v, float& lo, float& hi) {
    asm("mov.b64 {%0, %1}, %2;" : "=f"(lo), "=f"(hi) : "l"(v));
}

// ---------------------------------------------------------------------------
// Main kernel: y = relu(x @ Wfin + bias), Wfin already scaled.
// 128 independent [B,16]@[16,16] GEMMs, one per residue rho = r mod 128.
//   y[row, (rho+3+128m) & 2047] = sum_t x[row, rho+128t] * Wfin[t][m][rho]
// Block: 256 threads = 2 groups x 128 rho-lanes; each thread: 8 rows (4 f32x2
// pairs) x 16 outputs. W in smem ([t][m][rho] -> conflict-free LDS). Output
// staged through smem so final global stores are aligned float4.
// ---------------------------------------------------------------------------
__global__ void __launch_bounds__(THREADS, 1)
k_main(const float* __restrict__ x, const float* __restrict__ bias,
       float* __restrict__ y) {
    extern __shared__ float smem[];  // 32768 floats = 128 KB

    // Cooperative load of Wfin into smem (float4)
    {
        const float4* src = (const float4*)g_Wfin;
        float4* dst = (float4*)smem;
#pragma unroll
        for (int i = threadIdx.x; i < (K * K * 128) / 4; i += THREADS) dst[i] = src[i];
    }
    __syncthreads();

    const int rho = threadIdx.x & 127;
    const int grp = threadIdx.x >> 7;                     // 0 or 1
    const int row0 = blockIdx.x * ROWS_PER_BLOCK + grp * 8;
    const float* xp = x + (size_t)row0 * N + rho;

    unsigned long long acc[4][16];
#pragma unroll
    for (int p = 0; p < 4; p++)
#pragma unroll
        for (int m = 0; m < 16; m++) acc[p][m] = 0ull;

#pragma unroll
    for (int t = 0; t < 16; t++) {
        float xv[8];
#pragma unroll
        for (int j = 0; j < 8; j++) xv[j] = __ldcs(xp + (size_t)j * N + t * 128);
        unsigned long long px[4];
#pragma unroll
        for (int p = 0; p < 4; p++) px[p] = pack2(xv[2 * p], xv[2 * p + 1]);

        const float* wrow = smem + t * 16 * 128 + rho;
#pragma unroll
        for (int m = 0; m < 16; m++) {
            float w = wrow[m * 128];
            unsigned long long ww = pack2(w, w);
#pragma unroll
            for (int p = 0; p < 4; p++) acc[p][m] = fma2(px[p], ww, acc[p][m]);
        }
    }

    // Done reading W; reuse smem as output staging: [16 rows][2048 cols]
    __syncthreads();
#pragma unroll
    for (int m = 0; m < 16; m++) {
        int c = (rho + 3 + 128 * m) & (N - 1);
        float bv = __ldg(bias + c);
#pragma unroll
        for (int p = 0; p < 4; p++) {
            float lo, hi;
            unpack2(acc[p][m], lo, hi);
            lo = fmaxf(lo + bv, 0.f);
            hi = fmaxf(hi + bv, 0.f);
            int jr = grp * 8 + 2 * p;
            smem[(size_t)jr * N + c] = lo;
            smem[(size_t)(jr + 1) * N + c] = hi;
        }
    }
    __syncthreads();

    // Coalesced, aligned float4 writeout of the 16-row tile
    {
        const float4* s4 = (const float4*)smem;
        float4* o4 = (float4*)(y + (size_t)blockIdx.x * ROWS_PER_BLOCK * N);
#pragma unroll
        for (int i = threadIdx.x; i < ROWS_PER_BLOCK * N / 4; i += THREADS) o4[i] = s4[i];
    }
}

// ---------------------------------------------------------------------------
// Launch
// Inputs (metadata order): x, vals0, vals1, vals2, rows0, cols0, rows1, cols1,
//                          rows2, cols2, scaling, bias
// ---------------------------------------------------------------------------
extern "C" void kernel_launch(void* const* d_in, const int* in_sizes, int n_in,
                              void* d_out, int out_size) {
    const float* x       = (const float*)d_in[0];
    const float* v0      = (const float*)d_in[1];
    const float* v1      = (const float*)d_in[2];
    const float* v2      = (const float*)d_in[3];
    const float* scaling = (const float*)d_in[10];
    const float* bias    = (const float*)d_in[11];
    float* y = (float*)d_out;

    k_compose1<<<N / 128, 128>>>(v0, v1);
    k_compose2<<<N / 128, 128>>>(v2, scaling);

    cudaFuncSetAttribute(k_main, cudaFuncAttributeMaxDynamicSharedMemorySize, 131072);
    k_main<<<BATCH / ROWS_PER_BLOCK, THREADS, 131072>>>(x, bias, y);
}

// round 2
// speedup vs baseline: 1.3290x; 1.3290x over previous
#include <cuda_runtime.h>

#define N 2048
#define K 16
#define BATCH 16384
#define ROWS_PER_BLOCK 16
#define THREADS 512

// Scratch for composed factors (static device globals: allocation-free)
__device__ float g_W01[N * K];
// Final composed weights in [t][m][rho] layout: index (t*16+m)*128 + rho
__device__ float g_Wfin[K * K * 128];

// ---------------------------------------------------------------------------
// Precompute stage 1: W01 = W0 @ W1, one thread per (r, s) output.
// W0: r -> a = (r + 128*k0) % N,      val0[r*16+k0]
// W1: a -> b = (a + 128*k1 + 1) % N,  val1[a*16+k1]
// => W01[r, s] lives at b = (r + 128*s + 1) % N,  s = (k0+k1) & 15
// ---------------------------------------------------------------------------
__global__ void k_compose1(const float* __restrict__ v0, const float* __restrict__ v1) {
    int tid = blockIdx.x * blockDim.x + threadIdx.x;   // 0 .. 32767
    int r = tid >> 4;
    int s = tid & 15;
    float acc = 0.f;
#pragma unroll
    for (int k0 = 0; k0 < K; k0++) {
        int arow = (r + 128 * k0) & (N - 1);
        acc = fmaf(v0[r * K + k0], v1[arow * K + ((s - k0) & (K - 1))], acc);
    }
    g_W01[r * K + s] = acc;
}

// ---------------------------------------------------------------------------
// Precompute stage 2: W012 = W01 @ W2, folded with `scaling`, written into
// the main kernel's [t][m][rho] layout. One thread per (r, s).
// W01: r -> b = (r + 128*s01 + 1) % N
// W2:  b -> c = (b + 128*k2 + 2) % N  => c = (r + 128*s + 3) % N
// Main-kernel mapping: r = rho + 128*t, m = (t + s) & 15
// ---------------------------------------------------------------------------
__global__ void k_compose2(const float* __restrict__ v2, const float* __restrict__ scaling) {
    int tid = blockIdx.x * blockDim.x + threadIdx.x;
    int r = tid >> 4;
    int s = tid & 15;
    float sc = scaling[0];
    float acc = 0.f;
#pragma unroll
    for (int s01 = 0; s01 < K; s01++) {
        int brow = (r + 128 * s01 + 1) & (N - 1);
        acc = fmaf(g_W01[r * K + s01], v2[brow * K + ((s - s01) & (K - 1))], acc);
    }
    int rho = r & 127;
    int t = r >> 7;
    int m = (t + s) & (K - 1);
    g_Wfin[(t * 16 + m) * 128 + rho] = sc * acc;
}

// ---------------------------------------------------------------------------
// Packed f32x2 helpers (dual-rate FMA on sm_103a, only reachable via PTX)
// ---------------------------------------------------------------------------
__device__ __forceinline__ unsigned long long fma2(unsigned long long a,
                                                   unsigned long long b,
                                                   unsigned long long c) {
    unsigned long long d;
    asm("fma.rn.f32x2 %0, %1, %2, %3;" : "=l"(d) : "l"(a), "l"(b), "l"(c));
    return d;
}
__device__ __forceinline__ unsigned long long pack2(float lo, float hi) {
    unsigned long long r;
    asm("mov.b64 %0, {%1, %2};" : "=l"(r) : "f"(lo), "f"(hi));
    return r;
}
__device__ __forceinline__ void unpack2(unsigned long long v, float& lo, float& hi) {
    asm("mov.b64 {%0, %1}, %2;" : "=f"(lo), "=f"(hi) : "l"(v));
}

// ---------------------------------------------------------------------------
// Main kernel: y = relu(x @ Wfin + bias), Wfin already scaled.
// 128 independent [B,16]@[16,16] GEMMs, one per residue rho = r mod 128:
//   y[row, (rho+3+128m) & 2047] = sum_t x[row, rho+128t] * Wfin[t][m][rho]
//
// Block: 512 threads = 4 row-groups x 128 rho-lanes. Each thread handles
// 4 batch rows (2 f32x2 pairs) x 16 outputs -> 16 rows per block, 16 warps/SM.
// Software prefetch: x loads for t+1 issued before the FMA block of t.
// W in smem ([t][m][rho] -> conflict-free LDS, broadcast-free layout).
// Output staged through smem so final global stores are aligned float4.
// ---------------------------------------------------------------------------
__global__ void __launch_bounds__(THREADS, 1)
k_main(const float* __restrict__ x, const float* __restrict__ bias,
       float* __restrict__ y) {
    extern __shared__ float smem[];  // 32768 floats = 128 KB

    // Cooperative load of Wfin into smem (float4)
    {
        const float4* src = (const float4*)g_Wfin;
        float4* dst = (float4*)smem;
#pragma unroll
        for (int i = threadIdx.x; i < (K * K * 128) / 4; i += THREADS) dst[i] = src[i];
    }
    __syncthreads();

    const int rho = threadIdx.x & 127;
    const int grp = threadIdx.x >> 7;                       // 0..3
    const size_t row0 = (size_t)blockIdx.x * ROWS_PER_BLOCK + grp * 4;
    const float* xp = x + row0 * N + rho;

    unsigned long long acc[2][16];
#pragma unroll
    for (int p = 0; p < 2; p++)
#pragma unroll
        for (int m = 0; m < 16; m++) acc[p][m] = 0ull;

    float cur[4], nxt[4];
#pragma unroll
    for (int j = 0; j < 4; j++) cur[j] = __ldcs(xp + (size_t)j * N);

#pragma unroll
    for (int t = 0; t < 16; t++) {
        // Prefetch next t's x values before consuming current ones
        if (t < 15) {
#pragma unroll
            for (int j = 0; j < 4; j++)
                nxt[j] = __ldcs(xp + (size_t)j * N + (t + 1) * 128);
        }
        unsigned long long px0 = pack2(cur[0], cur[1]);
        unsigned long long px1 = pack2(cur[2], cur[3]);

        const float* wrow = smem + t * (16 * 128) + rho;
#pragma unroll
        for (int m = 0; m < 16; m++) {
            float w = wrow[m * 128];
            unsigned long long ww = pack2(w, w);
            acc[0][m] = fma2(px0, ww, acc[0][m]);
            acc[1][m] = fma2(px1, ww, acc[1][m]);
        }
#pragma unroll
        for (int j = 0; j < 4; j++) cur[j] = nxt[j];
    }

    // Done reading W; reuse smem as output staging: [16 rows][2048 cols]
    __syncthreads();
#pragma unroll
    for (int m = 0; m < 16; m++) {
        int c = (rho + 3 + (m << 7)) & (N - 1);
        float bv = __ldg(bias + c);
        float l0, h0, l1, h1;
        unpack2(acc[0][m], l0, h0);
        unpack2(acc[1][m], l1, h1);
        int jr = grp * 4;
        smem[(size_t)jr * N + c]       = fmaxf(l0 + bv, 0.f);
        smem[(size_t)(jr + 1) * N + c] = fmaxf(h0 + bv, 0.f);
        smem[(size_t)(jr + 2) * N + c] = fmaxf(l1 + bv, 0.f);
        smem[(size_t)(jr + 3) * N + c] = fmaxf(h1 + bv, 0.f);
    }
    __syncthreads();

    // Coalesced, aligned float4 writeout of the 16-row tile
    {
        const float4* s4 = (const float4*)smem;
        float4* o4 = (float4*)(y + (size_t)blockIdx.x * ROWS_PER_BLOCK * N);
#pragma unroll
        for (int i = threadIdx.x; i < ROWS_PER_BLOCK * N / 4; i += THREADS) o4[i] = s4[i];
    }
}

// ---------------------------------------------------------------------------
// Launch
// Inputs (metadata order): x, vals0, vals1, vals2, rows0, cols0, rows1, cols1,
//                          rows2, cols2, scaling, bias
// ---------------------------------------------------------------------------
extern "C" void kernel_launch(void* const* d_in, const int* in_sizes, int n_in,
                              void* d_out, int out_size) {
    const float* x       = (const float*)d_in[0];
    const float* v0      = (const float*)d_in[1];
    const float* v1      = (const float*)d_in[2];
    const float* v2      = (const float*)d_in[3];
    const float* scaling = (const float*)d_in[10];
    const float* bias    = (const float*)d_in[11];
    float* y = (float*)d_out;

    k_compose1<<<(N * K) / 256, 256>>>(v0, v1);
    k_compose2<<<(N * K) / 256, 256>>>(v2, scaling);

    cudaFuncSetAttribute(k_main, cudaFuncAttributeMaxDynamicSharedMemorySize, 131072);
    k_main<<<BATCH / ROWS_PER_BLOCK, THREADS, 131072>>>(x, bias, y);
}

// round 3
// speedup vs baseline: 1.4070x; 1.0587x over previous
#include <cuda_runtime.h>

#define N 2048
#define K 16
#define BATCH 16384
#define ROWS_PER_BLOCK 16
#define THREADS 512
#define GRID_MAIN 152
#define NTILES (BATCH / ROWS_PER_BLOCK)

// Final composed weights in [t][m][rho] layout: index (t*16+m)*128 + rho
__device__ float g_Wfin[K * K * 128];

// ---------------------------------------------------------------------------
// Fused precompute: Wfin = scaling * (W0 @ W1 @ W2), one kernel.
// Block = 256 threads = 16 r_local x 16 s. W01 row staged in smem.
// W0: r -> a=(r+128k0)%N ; W1: a -> b=(a+128k1+1)%N ; W2: b -> c=(b+128k2+2)%N
// Composed: c = (r + 128*s + 3) % N. Layout: r = rho+128t, m=(t+s)&15.
// ---------------------------------------------------------------------------
__global__ void k_compose(const float* __restrict__ v0, const float* __restrict__ v1,
                          const float* __restrict__ v2, const float* __restrict__ scaling) {
    __shared__ float w01[16][17];
    int s  = threadIdx.x & 15;
    int rl = threadIdx.x >> 4;               // 0..15
    int r  = blockIdx.x * 16 + rl;

    float acc = 0.f;
#pragma unroll
    for (int k0 = 0; k0 < K; k0++) {
        int arow = (r + 128 * k0) & (N - 1);
        acc = fmaf(v0[r * K + k0], v1[arow * K + ((s - k0) & (K - 1))], acc);
    }
    w01[rl][s] = acc;
    __syncthreads();

    float sc = scaling[0];
    float acc2 = 0.f;
#pragma unroll
    for (int s01 = 0; s01 < K; s01++) {
        int brow = (r + 128 * s01 + 1) & (N - 1);
        acc2 = fmaf(w01[rl][s01], v2[brow * K + ((s - s01) & (K - 1))], acc2);
    }
    int rho = r & 127;
    int t   = r >> 7;
    int m   = (t + s) & (K - 1);
    g_Wfin[(t * 16 + m) * 128 + rho] = sc * acc2;
}

// ---------------------------------------------------------------------------
// Packed f32x2 helpers (dual-rate FMA on sm_103a, only reachable via PTX)
// ---------------------------------------------------------------------------
__device__ __forceinline__ unsigned long long fma2(unsigned long long a,
                                                   unsigned long long b,
                                                   unsigned long long c) {
    unsigned long long d;
    asm("fma.rn.f32x2 %0, %1, %2, %3;" : "=l"(d) : "l"(a), "l"(b), "l"(c));
    return d;
}
__device__ __forceinline__ unsigned long long pack2(float lo, float hi) {
    unsigned long long r;
    asm("mov.b64 %0, {%1, %2};" : "=l"(r) : "f"(lo), "f"(hi));
    return r;
}
__device__ __forceinline__ void unpack2(unsigned long long v, float& lo, float& hi) {
    asm("mov.b64 {%0, %1}, %2;" : "=f"(lo), "=f"(hi) : "l"(v));
}

// ---------------------------------------------------------------------------
// Persistent main kernel: y = relu(x @ Wfin + bias).
//   y[row, (rho+3+128m) & 2047] = sum_t x[row, rho+128t] * Wfin[t][m][rho]
//
// Grid = 152 persistent blocks (1 CTA/SM), each strides over 16-row tiles.
// W (128 KB) loaded into smem ONCE per block and kept resident; a 64 KB
// half-tile staging buffer makes all global writes aligned float4.
// 512 threads = 4 row-groups x 128 rho-lanes; 4 rows/thread (2 f32x2 pairs)
// x 16 outputs. Depth-2 software prefetch on x keeps ~16 KB/SM in flight.
// ---------------------------------------------------------------------------
#define SMEM_W      0
#define SMEM_STAGE  (K * K * 128)          // 32768 floats
#define SMEM_FLOATS (SMEM_STAGE + 8 * N)   // + 16384 floats -> 192 KB

__global__ void __launch_bounds__(THREADS, 1)
k_main(const float* __restrict__ x, const float* __restrict__ bias,
       float* __restrict__ y) {
    extern __shared__ float smem[];

    // Load Wfin once (float4)
    {
        const float4* src = (const float4*)g_Wfin;
        float4* dst = (float4*)(smem + SMEM_W);
#pragma unroll
        for (int i = threadIdx.x; i < (K * K * 128) / 4; i += THREADS) dst[i] = src[i];
    }
    __syncthreads();

    const int rho = threadIdx.x & 127;
    const int grp = threadIdx.x >> 7;        // 0..3  (rows grp*4 .. grp*4+3)
    const int half_of_grp = grp >> 1;        // 0 for rows 0-7, 1 for rows 8-15
    const int row_in_stage0 = (grp & 1) * 4; // row offset inside the 8-row stage

    for (int tile = blockIdx.x; tile < NTILES; tile += GRID_MAIN) {
        const float* xp = x + ((size_t)tile * ROWS_PER_BLOCK + grp * 4) * N + rho;

        unsigned long long acc[2][16];
#pragma unroll
        for (int p = 0; p < 2; p++)
#pragma unroll
            for (int m = 0; m < 16; m++) acc[p][m] = 0ull;

        // Depth-2 pipelined x loads
        float xb[3][4];
#pragma unroll
        for (int j = 0; j < 4; j++) xb[0][j] = __ldcs(xp + (size_t)j * N);
#pragma unroll
        for (int j = 0; j < 4; j++) xb[1][j] = __ldcs(xp + (size_t)j * N + 128);

#pragma unroll
        for (int t = 0; t < 16; t++) {
            if (t < 14) {
#pragma unroll
                for (int j = 0; j < 4; j++)
                    xb[(t + 2) % 3][j] = __ldcs(xp + (size_t)j * N + (t + 2) * 128);
            }
            const float* cur = xb[t % 3];
            unsigned long long px0 = pack2(cur[0], cur[1]);
            unsigned long long px1 = pack2(cur[2], cur[3]);

            const float* wrow = smem + SMEM_W + t * (16 * 128) + rho;
#pragma unroll
            for (int m = 0; m < 16; m++) {
                float w = wrow[m * 128];
                unsigned long long ww = pack2(w, w);
                acc[0][m] = fma2(px0, ww, acc[0][m]);
                acc[1][m] = fma2(px1, ww, acc[1][m]);
            }
        }

        // Epilogue in two 8-row halves through the 64 KB staging buffer
        float* stage = smem + SMEM_STAGE;
#pragma unroll
        for (int h = 0; h < 2; h++) {
            if (half_of_grp == h) {
#pragma unroll
                for (int m = 0; m < 16; m++) {
                    int c = (rho + 3 + (m << 7)) & (N - 1);
                    float bv = __ldg(bias + c);
                    float l0, h0, l1, h1;
                    unpack2(acc[0][m], l0, h0);
                    unpack2(acc[1][m], l1, h1);
                    float* sp = stage + (size_t)row_in_stage0 * N + c;
                    sp[0]     = fmaxf(l0 + bv, 0.f);
                    sp[N]     = fmaxf(h0 + bv, 0.f);
                    sp[2 * N] = fmaxf(l1 + bv, 0.f);
                    sp[3 * N] = fmaxf(h1 + bv, 0.f);
                }
            }
            __syncthreads();
            // Aligned float4 streaming writeout of 8 rows
            {
                const float4* s4 = (const float4*)stage;
                float4* o4 = (float4*)(y + ((size_t)tile * ROWS_PER_BLOCK + h * 8) * N);
#pragma unroll
                for (int i = threadIdx.x; i < 8 * N / 4; i += THREADS)
                    __stcs(o4 + i, s4[i]);
            }
            __syncthreads();
        }
    }
}

// ---------------------------------------------------------------------------
// Launch
// Inputs (metadata order): x, vals0, vals1, vals2, rows0, cols0, rows1, cols1,
//                          rows2, cols2, scaling, bias
// ---------------------------------------------------------------------------
extern "C" void kernel_launch(void* const* d_in, const int* in_sizes, int n_in,
                              void* d_out, int out_size) {
    const float* x       = (const float*)d_in[0];
    const float* v0      = (const float*)d_in[1];
    const float* v1      = (const float*)d_in[2];
    const float* v2      = (const float*)d_in[3];
    const float* scaling = (const float*)d_in[10];
    const float* bias    = (const float*)d_in[11];
    float* y = (float*)d_out;

    k_compose<<<N / 16, 256>>>(v0, v1, v2, scaling);

    cudaFuncSetAttribute(k_main, cudaFuncAttributeMaxDynamicSharedMemorySize,
                         SMEM_FLOATS * sizeof(float));
    k_main<<<GRID_MAIN, THREADS, SMEM_FLOATS * sizeof(float)>>>(x, bias, y);
}

// round 4
// speedup vs baseline: 1.4186x; 1.0083x over previous
#include <cuda_runtime.h>

#define N 2048
#define K 16
#define BATCH 16384
#define ROWS_PER_BLOCK 16
#define THREADS 512
#define GRID_MAIN 152
#define NTILES (BATCH / ROWS_PER_BLOCK)

// Final composed weights, layout [t][m4][rho][4]:
//   g_Wfin[((t*4 + (m>>2))*128 + rho)*4 + (m&3)]
__device__ float g_Wfin[K * K * 128];

// ---------------------------------------------------------------------------
// Fused precompute: Wfin = scaling * (W0 @ W1 @ W2).
// Block = 256 threads = 16 r_local x 16 s; W01 row staged in smem.
// Composed pattern: c = (r + 128*s + 3) % N; r = rho + 128*t, m = (t+s)&15.
// ---------------------------------------------------------------------------
__global__ void k_compose(const float* __restrict__ v0, const float* __restrict__ v1,
                          const float* __restrict__ v2, const float* __restrict__ scaling) {
    __shared__ float w01[16][17];
    int s  = threadIdx.x & 15;
    int rl = threadIdx.x >> 4;
    int r  = blockIdx.x * 16 + rl;

    float acc = 0.f;
#pragma unroll
    for (int k0 = 0; k0 < K; k0++) {
        int arow = (r + 128 * k0) & (N - 1);
        acc = fmaf(v0[r * K + k0], v1[arow * K + ((s - k0) & (K - 1))], acc);
    }
    w01[rl][s] = acc;
    __syncthreads();

    float sc = scaling[0];
    float acc2 = 0.f;
#pragma unroll
    for (int s01 = 0; s01 < K; s01++) {
        int brow = (r + 128 * s01 + 1) & (N - 1);
        acc2 = fmaf(w01[rl][s01], v2[brow * K + ((s - s01) & (K - 1))], acc2);
    }
    int rho = r & 127;
    int t   = r >> 7;
    int m   = (t + s) & (K - 1);
    g_Wfin[((t * 4 + (m >> 2)) * 128 + rho) * 4 + (m & 3)] = sc * acc2;
}

// ---------------------------------------------------------------------------
// Packed f32x2 helpers
// ---------------------------------------------------------------------------
__device__ __forceinline__ unsigned long long fma2(unsigned long long a,
                                                   unsigned long long b,
                                                   unsigned long long c) {
    unsigned long long d;
    asm("fma.rn.f32x2 %0, %1, %2, %3;" : "=l"(d) : "l"(a), "l"(b), "l"(c));
    return d;
}
__device__ __forceinline__ unsigned long long pack2(float lo, float hi) {
    unsigned long long r;
    asm("mov.b64 %0, {%1, %2};" : "=l"(r) : "f"(lo), "f"(hi));
    return r;
}
__device__ __forceinline__ void unpack2(unsigned long long v, float& lo, float& hi) {
    asm("mov.b64 {%0, %1}, %2;" : "=f"(lo), "=f"(hi) : "l"(v));
}

__device__ __forceinline__ void cp_async16(unsigned smem_addr, const void* gptr) {
    asm volatile("cp.async.cg.shared.global [%0], [%1], 16;" :: "r"(smem_addr), "l"(gptr));
}
__device__ __forceinline__ void cp_commit() {
    asm volatile("cp.async.commit_group;");
}
__device__ __forceinline__ void cp_wait2() {
    asm volatile("cp.async.wait_group 2;");
}

// ---------------------------------------------------------------------------
// Persistent main kernel: y = relu(x @ Wfin + bias).
//   y[row, (rho+3+128m)&2047] = sum_t x[row, rho+128t] * Wfin[t][m][rho]
//
// 152 persistent CTAs (1/SM), 512 thr = 4 row-groups x 128 rho-lanes,
// 4 rows/thread (2 f32x2 pairs) x 16 outputs.
// x streamed through a 4-stage cp.async smem ring (8 KB/stage, 32 KB in
// flight, continuous across tile boundaries). W resident in smem (128 KB,
// [t][m4][rho][4] -> LDS.128, conflict-free). Bias cached in smem.
// Scattered-but-warp-contiguous __stcs writeout (no staging buffer).
// ---------------------------------------------------------------------------
#define SM_W     0
#define SM_X     (32 * 1024)                 // floats: 32768
#define SM_BIAS  (SM_X + 4 * ROWS_PER_BLOCK * 128)  // + 8192 = 40960
#define SM_FLOATS (SM_BIAS + N)              // 43008 floats = 168 KB

__global__ void __launch_bounds__(THREADS, 1)
k_main(const float* __restrict__ x, const float* __restrict__ bias,
       float* __restrict__ y) {
    extern __shared__ float smem[];

    // Resident W load (float4) + bias
    {
        const float4* src = (const float4*)g_Wfin;
        float4* dst = (float4*)(smem + SM_W);
#pragma unroll
        for (int i = threadIdx.x; i < (K * K * 128) / 4; i += THREADS) dst[i] = src[i];
        for (int i = threadIdx.x; i < N; i += THREADS) smem[SM_BIAS + i] = bias[i];
    }

    const int tid  = threadIdx.x;
    const int rho  = tid & 127;
    const int grp  = tid >> 7;              // 0..3 -> rows grp*4 .. grp*4+3
    // cp.async assignment: thread copies 16B of row crow, chunk cchunk
    const int crow   = tid >> 5;            // 0..15
    const int cchunk = (tid & 31) * 4;      // float offset within 128

    const unsigned sx_base =
        (unsigned)__cvta_generic_to_shared(smem + SM_X) + (crow * 128 + cchunk) * 4;

    // Issue one pipeline stage: columns st*128.. of 16 rows of tile `tl`
    auto issue = [&](int tl, int st) {
        const float* src = x + ((size_t)tl * ROWS_PER_BLOCK + crow) * N + st * 128 + cchunk;
        cp_async16(sx_base + ((st & 3) * 2048) * 4, src);
    };

    int tile = blockIdx.x;
    if (tile < NTILES) {
        issue(tile, 0); cp_commit();
        issue(tile, 1); cp_commit();
        issue(tile, 2); cp_commit();
    }
    __syncthreads();

    for (; tile < NTILES; tile += GRID_MAIN) {
        const int next = tile + GRID_MAIN;

        unsigned long long acc[2][16];
#pragma unroll
        for (int p = 0; p < 2; p++)
#pragma unroll
            for (int m = 0; m < 16; m++) acc[p][m] = 0ull;

#pragma unroll
        for (int t = 0; t < 16; t++) {
            cp_wait2();
            __syncthreads();

            // Keep the pipe full: issue stage t+3 (this tile or next tile)
            {
                int st = t + 3;
                if (st < 16) issue(tile, st);
                else if (next < NTILES) issue(next, st - 16);
                cp_commit();
            }

            // x for this stage: 4 rows at this thread's rho
            const float* xs = smem + SM_X + (t & 3) * 2048 + grp * 4 * 128 + rho;
            unsigned long long px0 = pack2(xs[0], xs[128]);
            unsigned long long px1 = pack2(xs[256], xs[384]);

            const float* wrow = smem + SM_W + (t * 4 * 128) * 4 + rho * 4;
#pragma unroll
            for (int m4 = 0; m4 < 4; m4++) {
                float4 w = *(const float4*)(wrow + m4 * 512);
                unsigned long long w0 = pack2(w.x, w.x);
                unsigned long long w1 = pack2(w.y, w.y);
                unsigned long long w2 = pack2(w.z, w.z);
                unsigned long long w3 = pack2(w.w, w.w);
                acc[0][4 * m4 + 0] = fma2(px0, w0, acc[0][4 * m4 + 0]);
                acc[1][4 * m4 + 0] = fma2(px1, w0, acc[1][4 * m4 + 0]);
                acc[0][4 * m4 + 1] = fma2(px0, w1, acc[0][4 * m4 + 1]);
                acc[1][4 * m4 + 1] = fma2(px1, w1, acc[1][4 * m4 + 1]);
                acc[0][4 * m4 + 2] = fma2(px0, w2, acc[0][4 * m4 + 2]);
                acc[1][4 * m4 + 2] = fma2(px1, w2, acc[1][4 * m4 + 2]);
                acc[0][4 * m4 + 3] = fma2(px0, w3, acc[0][4 * m4 + 3]);
                acc[1][4 * m4 + 3] = fma2(px1, w3, acc[1][4 * m4 + 3]);
            }
        }

        // Epilogue: bias + relu + direct streaming stores.
        // For fixed (m,row) the 128 rho-lanes of a group write 512 contiguous
        // bytes (offset by 12 B) -> near-perfectly coalesced.
        float* yr = y + ((size_t)tile * ROWS_PER_BLOCK + grp * 4) * N;
#pragma unroll
        for (int m = 0; m < 16; m++) {
            int c = (rho + 3 + (m << 7)) & (N - 1);
            float bv = smem[SM_BIAS + c];
            float l0, h0, l1, h1;
            unpack2(acc[0][m], l0, h0);
            unpack2(acc[1][m], l1, h1);
            __stcs(yr + c,         fmaxf(l0 + bv, 0.f));
            __stcs(yr + N + c,     fmaxf(h0 + bv, 0.f));
            __stcs(yr + 2 * N + c, fmaxf(l1 + bv, 0.f));
            __stcs(yr + 3 * N + c, fmaxf(h1 + bv, 0.f));
        }
    }
}

// ---------------------------------------------------------------------------
// Launch. Inputs: x, vals0, vals1, vals2, rows0, cols0, rows1, cols1,
//                 rows2, cols2, scaling, bias
// ---------------------------------------------------------------------------
extern "C" void kernel_launch(void* const* d_in, const int* in_sizes, int n_in,
                              void* d_out, int out_size) {
    const float* x       = (const float*)d_in[0];
    const float* v0      = (const float*)d_in[1];
    const float* v1      = (const float*)d_in[2];
    const float* v2      = (const float*)d_in[3];
    const float* scaling = (const float*)d_in[10];
    const float* bias    = (const float*)d_in[11];
    float* y = (float*)d_out;

    k_compose<<<N / 16, 256>>>(v0, v1, v2, scaling);

    cudaFuncSetAttribute(k_main, cudaFuncAttributeMaxDynamicSharedMemorySize,
                         SM_FLOATS * sizeof(float));
    k_main<<<GRID_MAIN, THREADS, SM_FLOATS * sizeof(float)>>>(x, bias, y);
}

// round 5
// speedup vs baseline: 1.7761x; 1.2520x over previous
#include <cuda_runtime.h>

#define N 2048
#define K 16
#define BATCH 16384
#define RPB 16
#define THREADS 512
#define GRID_MAIN 152
#define NTILES (BATCH / RPB)
#define STAGES 6

// Final composed weights, layout [t][m4][rho][4]:
//   g_Wfin[((t*4 + (m>>2))*128 + rho)*4 + (m&3)]
__device__ float g_Wfin[K * K * 128];

// ---------------------------------------------------------------------------
// Fused precompute: Wfin = scaling * (W0 @ W1 @ W2).
// Composed pattern: c = (r + 128*s + 3) % N; r = rho + 128*t, m = (t+s)&15.
// ---------------------------------------------------------------------------
__global__ void k_compose(const float* __restrict__ v0, const float* __restrict__ v1,
                          const float* __restrict__ v2, const float* __restrict__ scaling) {
    __shared__ float w01[16][17];
    int s  = threadIdx.x & 15;
    int rl = threadIdx.x >> 4;
    int r  = blockIdx.x * 16 + rl;

    float acc = 0.f;
#pragma unroll
    for (int k0 = 0; k0 < K; k0++) {
        int arow = (r + 128 * k0) & (N - 1);
        acc = fmaf(v0[r * K + k0], v1[arow * K + ((s - k0) & (K - 1))], acc);
    }
    w01[rl][s] = acc;
    __syncthreads();

    float sc = scaling[0];
    float acc2 = 0.f;
#pragma unroll
    for (int s01 = 0; s01 < K; s01++) {
        int brow = (r + 128 * s01 + 1) & (N - 1);
        acc2 = fmaf(w01[rl][s01], v2[brow * K + ((s - s01) & (K - 1))], acc2);
    }
    int rho = r & 127;
    int t   = r >> 7;
    int m   = (t + s) & (K - 1);
    g_Wfin[((t * 4 + (m >> 2)) * 128 + rho) * 4 + (m & 3)] = sc * acc2;
}

// ---------------------------------------------------------------------------
// Packed f32x2 + cp.async helpers
// ---------------------------------------------------------------------------
__device__ __forceinline__ unsigned long long fma2(unsigned long long a,
                                                   unsigned long long b,
                                                   unsigned long long c) {
    unsigned long long d;
    asm("fma.rn.f32x2 %0, %1, %2, %3;" : "=l"(d) : "l"(a), "l"(b), "l"(c));
    return d;
}
__device__ __forceinline__ unsigned long long pack2(float lo, float hi) {
    unsigned long long r;
    asm("mov.b64 %0, {%1, %2};" : "=l"(r) : "f"(lo), "f"(hi));
    return r;
}
__device__ __forceinline__ void unpack2(unsigned long long v, float& lo, float& hi) {
    asm("mov.b64 {%0, %1}, %2;" : "=f"(lo), "=f"(hi) : "l"(v));
}
__device__ __forceinline__ void cp_async16(unsigned smem_addr, const void* gptr) {
    asm volatile("cp.async.cg.shared.global [%0], [%1], 16;"
                 :: "r"(smem_addr), "l"(gptr) : "memory");
}
__device__ __forceinline__ void cp_commit() {
    asm volatile("cp.async.commit_group;" ::: "memory");
}
__device__ __forceinline__ void cp_wait4() {
    asm volatile("cp.async.wait_group 4;" ::: "memory");
}

// ---------------------------------------------------------------------------
// Persistent main kernel: y = relu(x @ Wfin + bias).
//   y[row, (rho+3+128m)&2047] = sum_t x[row, rho+128t] * Wfin[t][m][rho]
//
// 152 persistent CTAs, 512 thr = 16 warps. NO block barriers in the loop:
// each warp owns a private 6-stage cp.async ring (512 B/stage = its own 4
// rows x its 32-rho window), so producer == consumer warp and wait_group +
// syncwarp is the only synchronization. 5 groups in flight per warp
// -> 40 KB/SM outstanding, issued continuously (warps slide freely).
// W resident in smem ([t][m4][rho][4] -> LDS.128), bias cached in smem.
// ---------------------------------------------------------------------------
#define SM_W      0
#define SM_X      (32 * 1024)                       // floats
#define SM_BIAS   (SM_X + 16 * STAGES * 128)        // + 12288 = 45056
#define SM_FLOATS (SM_BIAS + N)                     // 47104 floats = 184 KB

__global__ void __launch_bounds__(THREADS, 1)
k_main(const float* __restrict__ x, const float* __restrict__ bias,
       float* __restrict__ y) {
    extern __shared__ float smem[];

    // Resident W (float4) + bias
    {
        const float4* src = (const float4*)g_Wfin;
        float4* dst = (float4*)(smem + SM_W);
#pragma unroll
        for (int i = threadIdx.x; i < (K * K * 128) / 4; i += THREADS) dst[i] = src[i];
        for (int i = threadIdx.x; i < N; i += THREADS) smem[SM_BIAS + i] = bias[i];
    }
    __syncthreads();

    const int tid  = threadIdx.x;
    const int lane = tid & 31;
    const int warp = tid >> 5;
    const int grp  = warp >> 2;                 // 0..3 -> rows grp*4..grp*4+3
    const int wsub = warp & 3;                  // rho window
    const int rho  = wsub * 32 + lane;          // == tid & 127
    const int crow = lane >> 3;                 // 0..3: row this lane copies
    const int coff = (lane & 7) * 4;            // float offset in 32-float window

    float* ring = smem + SM_X + warp * (STAGES * 128);
    const unsigned ring_sa = (unsigned)__cvta_generic_to_shared(ring);

    // Issue column-block `st` of tile `tl` into ring slot `slot` (1 group)
    auto issue = [&](int tl, int st, int slot) {
        const float* src = x + ((size_t)tl * RPB + grp * 4 + crow) * N
                             + st * 128 + wsub * 32 + coff;
        cp_async16(ring_sa + (unsigned)(slot * 128 + crow * 32 + coff) * 4, src);
        cp_commit();
    };

    int tile = blockIdx.x;
    // Prologue: stages 0..4 -> slots 0..4 (5 groups in flight)
#pragma unroll
    for (int s = 0; s < STAGES - 1; s++) issue(tile, s, s);

    int rslot = 0, islot = STAGES - 1;

    for (; tile < NTILES; tile += GRID_MAIN) {
        const int next = tile + GRID_MAIN;

        unsigned long long acc[2][16];
#pragma unroll
        for (int p = 0; p < 2; p++)
#pragma unroll
            for (int m = 0; m < 16; m++) acc[p][m] = 0ull;

#pragma unroll
        for (int t = 0; t < 16; t++) {
            cp_wait4();
            __syncwarp();

            // x for this stage: this thread's 4 rows at its rho
            const float* xs = ring + rslot * 128;
            unsigned long long px0 = pack2(xs[lane],      xs[32 + lane]);
            unsigned long long px1 = pack2(xs[64 + lane], xs[96 + lane]);

            // Keep 5 groups in flight: issue global stage t+5 (rolls into the
            // next tile; harmless dummy re-read of current tile at the tail).
            {
                int st = t + (STAGES - 1);
                if (st < 16) issue(tile, st, islot);
                else issue(next < NTILES ? next : tile, st - 16, islot);
            }

            const float* wrow = smem + SM_W + t * 2048 + rho * 4;
#pragma unroll
            for (int m4 = 0; m4 < 4; m4++) {
                float4 w = *(const float4*)(wrow + m4 * 512);
                unsigned long long w0 = pack2(w.x, w.x);
                unsigned long long w1 = pack2(w.y, w.y);
                unsigned long long w2 = pack2(w.z, w.z);
                unsigned long long w3 = pack2(w.w, w.w);
                acc[0][4 * m4 + 0] = fma2(px0, w0, acc[0][4 * m4 + 0]);
                acc[1][4 * m4 + 0] = fma2(px1, w0, acc[1][4 * m4 + 0]);
                acc[0][4 * m4 + 1] = fma2(px0, w1, acc[0][4 * m4 + 1]);
                acc[1][4 * m4 + 1] = fma2(px1, w1, acc[1][4 * m4 + 1]);
                acc[0][4 * m4 + 2] = fma2(px0, w2, acc[0][4 * m4 + 2]);
                acc[1][4 * m4 + 2] = fma2(px1, w2, acc[1][4 * m4 + 2]);
                acc[0][4 * m4 + 3] = fma2(px0, w3, acc[0][4 * m4 + 3]);
                acc[1][4 * m4 + 3] = fma2(px1, w3, acc[1][4 * m4 + 3]);
            }

            rslot = (rslot == STAGES - 1) ? 0 : rslot + 1;
            islot = (islot == STAGES - 1) ? 0 : islot + 1;
        }

        // Epilogue: bias + relu + direct streaming stores (warp-contiguous).
        float* yr = y + ((size_t)tile * RPB + grp * 4) * N;
#pragma unroll
        for (int m = 0; m < 16; m++) {
            int c = (rho + 3 + (m << 7)) & (N - 1);
            float bv = smem[SM_BIAS + c];
            float l0, h0, l1, h1;
            unpack2(acc[0][m], l0, h0);
            unpack2(acc[1][m], l1, h1);
            __stcs(yr + c,         fmaxf(l0 + bv, 0.f));
            __stcs(yr + N + c,     fmaxf(h0 + bv, 0.f));
            __stcs(yr + 2 * N + c, fmaxf(l1 + bv, 0.f));
            __stcs(yr + 3 * N + c, fmaxf(h1 + bv, 0.f));
        }
    }
}

// ---------------------------------------------------------------------------
// Launch. Inputs: x, vals0, vals1, vals2, rows0, cols0, rows1, cols1,
//                 rows2, cols2, scaling, bias
// ---------------------------------------------------------------------------
extern "C" void kernel_launch(void* const* d_in, const int* in_sizes, int n_in,
                              void* d_out, int out_size) {
    const float* x       = (const float*)d_in[0];
    const float* v0      = (const float*)d_in[1];
    const float* v1      = (const float*)d_in[2];
    const float* v2      = (const float*)d_in[3];
    const float* scaling = (const float*)d_in[10];
    const float* bias    = (const float*)d_in[11];
    float* y = (float*)d_out;

    k_compose<<<N / 16, 256>>>(v0, v1, v2, scaling);

    cudaFuncSetAttribute(k_main, cudaFuncAttributeMaxDynamicSharedMemorySize,
                         SM_FLOATS * sizeof(float));
    k_main<<<GRID_MAIN, THREADS, SM_FLOATS * sizeof(float)>>>(x, bias, y);
}